// round 4
// baseline (speedup 1.0000x reference)
#include <cuda_runtime.h>

#define NS 4096
#define NBATCH 32
#define TPB 256

// pywt db4 dec filters, time-reversed (cross-correlation form)
__device__ __constant__ float cH0[8] = {
     0.23037781330885523f,  0.7148465705525415f,   0.6308807679295904f,
    -0.02798376941698385f, -0.18703481171888114f,  0.030841381835986965f,
     0.032883011666982945f, -0.010597401784997278f };
__device__ __constant__ float cH1[8] = {
    -0.010597401784997278f, -0.032883011666982945f, 0.030841381835986965f,
     0.18703481171888114f,  -0.02798376941698385f,  -0.6308807679295904f,
     0.7148465705525415f,   -0.23037781330885523f };

// Lowpass scratch planes, (B, T_k, 64) contiguous.
__device__ float g_scratch[8126464];
#define OFF_LO1 0
#define OFF_LO2 4194304
#define OFF_LO3 6291456
#define OFF_LO4 7340032
#define OFF_LO5 7864320

__device__ __forceinline__ int level_of(float sc) {
    int l = 2 + (int)rintf(sc * 3.0f);          // round-half-even, matches jnp.round
    return l < 2 ? 2 : (l > 5 ? 5 : l);
}

// One analysis level over full 64-feature rows; each thread owns a quarter-row
// (16 floats = 64 B). Writes lo_k to scratch, masked detail to its out plane
// (with zero tail), and accumulates into the high_freq plane:
//   DET==0 : hf = hi (all 4096 rows, zero tail included)
//   DET>=1 : hf[0..TOUT) += masked hi   (prefix rows, L2-hot RMW)
template <int TIN, int DET>
__global__ void __launch_bounds__(TPB)
level_kernel(const float* __restrict__ in, float* __restrict__ loOut,
             float* __restrict__ det, float* __restrict__ hf,
             const float* __restrict__ scores)
{
    const int TOUT = TIN / 2;
    int idx = blockIdx.x * TPB + threadIdx.x;
    const int q = idx & 3;                       // quarter-row: 4 float4 chunks
    const int n = (idx >> 2) & (NS - 1);
    const int b = idx >> 14;                     // 4096*4 = 16384 per batch

    float4* pd = (float4*)det + ((size_t)b * NS + n) * 16 + q * 4;
    float4* ph = (float4*)hf  + ((size_t)b * NS + n) * 16 + q * 4;

    if (n >= TOUT) {                             // zero tail of detail plane
        const float4 z = make_float4(0.f, 0.f, 0.f, 0.f);
        pd[0] = z; pd[1] = z; pd[2] = z; pd[3] = z;
        if (DET == 0) { ph[0] = z; ph[1] = z; ph[2] = z; ph[3] = z; }
        return;
    }

    const float4* pin = (const float4*)in + (size_t)b * TIN * 16 + q * 4;
    float4 lo[4], hi[4];
#pragma unroll
    for (int c = 0; c < 4; ++c) {
        lo[c] = make_float4(0.f, 0.f, 0.f, 0.f);
        hi[c] = make_float4(0.f, 0.f, 0.f, 0.f);
    }
#pragma unroll
    for (int t = 0; t < 8; ++t) {
        int r = 2 * n + t - 3;
        if (r >= 0 && r < TIN) {
            const float c0 = cH0[t], c1 = cH1[t];
            const float4* pr = pin + (size_t)r * 16;
#pragma unroll
            for (int c = 0; c < 4; ++c) {
                float4 v = __ldg(pr + c);
                lo[c].x = fmaf(c0, v.x, lo[c].x); lo[c].y = fmaf(c0, v.y, lo[c].y);
                lo[c].z = fmaf(c0, v.z, lo[c].z); lo[c].w = fmaf(c0, v.w, lo[c].w);
                hi[c].x = fmaf(c1, v.x, hi[c].x); hi[c].y = fmaf(c1, v.y, hi[c].y);
                hi[c].z = fmaf(c1, v.z, hi[c].z); hi[c].w = fmaf(c1, v.w, hi[c].w);
            }
        }
    }
    // per-feature activity mask: detail DET populated iff DET < lf (lf >= 2)
    if (DET >= 2) {
        const int f = q * 16;
#pragma unroll
        for (int c = 0; c < 4; ++c) {
            if (DET >= level_of(__ldg(scores + f + c * 4 + 0))) hi[c].x = 0.f;
            if (DET >= level_of(__ldg(scores + f + c * 4 + 1))) hi[c].y = 0.f;
            if (DET >= level_of(__ldg(scores + f + c * 4 + 2))) hi[c].z = 0.f;
            if (DET >= level_of(__ldg(scores + f + c * 4 + 3))) hi[c].w = 0.f;
        }
    }

    float4* pl = (float4*)loOut + ((size_t)b * TOUT + n) * 16 + q * 4;
#pragma unroll
    for (int c = 0; c < 4; ++c) {
        pl[c] = lo[c];
        pd[c] = hi[c];
    }
    if (DET == 0) {
#pragma unroll
        for (int c = 0; c < 4; ++c) ph[c] = hi[c];
    } else {
#pragma unroll
        for (int c = 0; c < 4; ++c) {
            float4 h = ph[c];
            h.x += hi[c].x; h.y += hi[c].y; h.z += hi[c].z; h.w += hi[c].w;
            ph[c] = h;
        }
    }
}

// Final: approx (plane 0) and low_freq (plane 7) via per-feature level select.
__global__ void __launch_bounds__(TPB)
final_kernel(float* __restrict__ out, const float* __restrict__ scores)
{
    int idx = blockIdx.x * TPB + threadIdx.x;
    const int q = idx & 3;
    const int s = (idx >> 2) & (NS - 1);
    const int b = idx >> 14;

    const size_t PLANE4 = (size_t)NBATCH * NS * 16;
    const size_t row4   = ((size_t)b * NS + s) * 16 + q * 4;

    const size_t offs[4] = { OFF_LO2, OFF_LO3, OFF_LO4, OFF_LO5 };
    const int f0 = q * 16;
    float4 a[4];
#pragma unroll
    for (int c = 0; c < 4; ++c) {
        float av[4];
#pragma unroll
        for (int j = 0; j < 4; ++j) {
            int f = f0 + c * 4 + j;
            int k = level_of(__ldg(scores + f)) - 2;     // 0..3
            int T = 1024 >> k;
            av[j] = (s < T)
                ? __ldg(g_scratch + offs[k] + ((size_t)b * T + s) * 64 + f)
                : 0.f;
        }
        a[c] = make_float4(av[0], av[1], av[2], av[3]);
    }
    float4* pa = (float4*)out + row4;               // approx
    float4* plw = (float4*)out + 7 * PLANE4 + row4; // low_freq
#pragma unroll
    for (int c = 0; c < 4; ++c) { pa[c] = a[c]; plw[c] = a[c]; }
}

extern "C" void kernel_launch(void* const* d_in, const int* in_sizes, int n_in,
                              void* d_out, int out_size)
{
    const float* x      = (const float*)d_in[0];
    const float* scores = (const float*)d_in[1];
    float* out          = (float*)d_out;

    float* scratch;
    cudaGetSymbolAddress((void**)&scratch, g_scratch);
    float* lo1 = scratch + OFF_LO1;
    float* lo2 = scratch + OFF_LO2;
    float* lo3 = scratch + OFF_LO3;
    float* lo4 = scratch + OFF_LO4;
    float* lo5 = scratch + OFF_LO5;

    const size_t PLANE = (size_t)NBATCH * NS * 64;
    float* hf = out + 6 * PLANE;
    const int grid = (NBATCH * NS * 4) / TPB;           // 2048 blocks

    level_kernel<4096, 0><<<grid, TPB>>>(x,   lo1, out + 1 * PLANE, hf, scores);
    level_kernel<2048, 1><<<grid, TPB>>>(lo1, lo2, out + 2 * PLANE, hf, scores);
    level_kernel<1024, 2><<<grid, TPB>>>(lo2, lo3, out + 3 * PLANE, hf, scores);
    level_kernel< 512, 3><<<grid, TPB>>>(lo3, lo4, out + 4 * PLANE, hf, scores);
    level_kernel< 256, 4><<<grid, TPB>>>(lo4, lo5, out + 5 * PLANE, hf, scores);
    final_kernel<<<grid, TPB>>>(out, scores);
}

// round 5
// speedup vs baseline: 1.8713x; 1.8713x over previous
#include <cuda_runtime.h>

#define NS 4096
#define NBATCH 32
#define TPB 256

// pywt db4 dec filters, time-reversed (cross-correlation form)
__device__ __constant__ float cH0[8] = {
     0.23037781330885523f,  0.7148465705525415f,   0.6308807679295904f,
    -0.02798376941698385f, -0.18703481171888114f,  0.030841381835986965f,
     0.032883011666982945f, -0.010597401784997278f };
__device__ __constant__ float cH1[8] = {
    -0.010597401784997278f, -0.032883011666982945f, 0.030841381835986965f,
     0.18703481171888114f,  -0.02798376941698385f,  -0.6308807679295904f,
     0.7148465705525415f,   -0.23037781330885523f };

// Lowpass scratch planes, (B, T_k, 64) contiguous.
__device__ float g_scratch[8126464];
#define OFF_LO1 0
#define OFF_LO2 4194304
#define OFF_LO3 6291456
#define OFF_LO4 7340032
#define OFF_LO5 7864320

__device__ __forceinline__ int level_of(float sc) {
    int l = 2 + (int)rintf(sc * 3.0f);          // round-half-even, matches jnp.round
    return l < 2 ? 2 : (l > 5 ? 5 : l);
}

// One analysis level over full 64-feature rows, ONE float4 per thread (the
// R3 mapping: regs ~32, high occupancy). Writes lo_k to scratch, masked
// detail to its out plane (zero tail), and folds into the high_freq plane:
//   DET==0 : hf = hi for all 4096 rows (tail zeros included)  — pure store
//   DET>=1 : hf[0..TOUT) += masked hi — prefix RMW, L2-hot (written by the
//            immediately preceding kernel). Each (b,n,f4) is owned by exactly
//            one thread and kernels are stream-ordered, so the RMW is safe.
template <int TIN, int DET>
__global__ void __launch_bounds__(TPB)
level_kernel(const float* __restrict__ in, float* __restrict__ loOut,
             float* __restrict__ det, float* __restrict__ hf,
             const float* __restrict__ scores)
{
    const int TOUT = TIN / 2;
    int idx = blockIdx.x * TPB + threadIdx.x;      // (b, n, f4)
    const int f4 = idx & 15;                       // 16 float4 chunks per row
    const int n  = (idx >> 4) & (NS - 1);
    const int b  = idx >> 16;                      // 4096*16 per batch

    float4* pd = (float4*)det + ((size_t)b * NS + n) * 16 + f4;
    float4* ph = (float4*)hf  + ((size_t)b * NS + n) * 16 + f4;

    if (n >= TOUT) {                               // zero tail of detail plane
        const float4 z = make_float4(0.f, 0.f, 0.f, 0.f);
        *pd = z;
        if (DET == 0) *ph = z;                     // hf tail zero once, at level 1
        return;
    }

    const float4* pin = (const float4*)in + (size_t)b * TIN * 16 + f4;
    float4 lo = make_float4(0.f, 0.f, 0.f, 0.f);
    float4 hi = make_float4(0.f, 0.f, 0.f, 0.f);
#pragma unroll
    for (int t = 0; t < 8; ++t) {
        int r = 2 * n + t - 3;
        if (r >= 0 && r < TIN) {
            float4 v = __ldg(pin + (size_t)r * 16);
            float c0 = cH0[t], c1 = cH1[t];
            lo.x = fmaf(c0, v.x, lo.x); lo.y = fmaf(c0, v.y, lo.y);
            lo.z = fmaf(c0, v.z, lo.z); lo.w = fmaf(c0, v.w, lo.w);
            hi.x = fmaf(c1, v.x, hi.x); hi.y = fmaf(c1, v.y, hi.y);
            hi.z = fmaf(c1, v.z, hi.z); hi.w = fmaf(c1, v.w, hi.w);
        }
    }
    // per-feature activity mask: detail DET populated iff DET < lf (lf >= 2)
    if (DET >= 2) {
        const int f = f4 * 4;
        if (DET >= level_of(__ldg(scores + f + 0))) hi.x = 0.f;
        if (DET >= level_of(__ldg(scores + f + 1))) hi.y = 0.f;
        if (DET >= level_of(__ldg(scores + f + 2))) hi.z = 0.f;
        if (DET >= level_of(__ldg(scores + f + 3))) hi.w = 0.f;
    }

    ((float4*)loOut)[((size_t)b * TOUT + n) * 16 + f4] = lo;
    *pd = hi;

    if (DET == 0) {
        *ph = hi;                                  // hf = det1
    } else {
        float4 h = *ph;                            // L2-hot prefix RMW
        h.x += hi.x; h.y += hi.y; h.z += hi.z; h.w += hi.w;
        *ph = h;
    }
}

// Final: approx (plane 0) and low_freq (plane 7) via per-feature level select.
__global__ void __launch_bounds__(TPB)
final_kernel(float* __restrict__ out, const float* __restrict__ scores)
{
    int idx = blockIdx.x * TPB + threadIdx.x;
    const int f4 = idx & 15;
    const int s  = (idx >> 4) & (NS - 1);
    const int b  = idx >> 16;

    const size_t PLANE4 = (size_t)NBATCH * NS * 16;      // float4 units
    const size_t row4   = ((size_t)b * NS + s) * 16 + f4;

    const size_t offs[4] = { OFF_LO2, OFF_LO3, OFF_LO4, OFF_LO5 };
    const int f = f4 * 4;
    float av[4];
#pragma unroll
    for (int j = 0; j < 4; ++j) {
        int k = level_of(__ldg(scores + f + j)) - 2;     // 0..3
        int T = 1024 >> k;
        av[j] = (s < T)
            ? __ldg(g_scratch + offs[k] + ((size_t)b * T + s) * 64 + f + j)
            : 0.f;
    }
    float4 a = make_float4(av[0], av[1], av[2], av[3]);
    ((float4*)out)[row4] = a;               // approx
    ((float4*)out)[7 * PLANE4 + row4] = a;  // low_freq
}

extern "C" void kernel_launch(void* const* d_in, const int* in_sizes, int n_in,
                              void* d_out, int out_size)
{
    const float* x      = (const float*)d_in[0];
    const float* scores = (const float*)d_in[1];
    float* out          = (float*)d_out;

    float* scratch;
    cudaGetSymbolAddress((void**)&scratch, g_scratch);
    float* lo1 = scratch + OFF_LO1;
    float* lo2 = scratch + OFF_LO2;
    float* lo3 = scratch + OFF_LO3;
    float* lo4 = scratch + OFF_LO4;
    float* lo5 = scratch + OFF_LO5;

    const size_t PLANE = (size_t)NBATCH * NS * 64;
    float* hf = out + 6 * PLANE;
    const int grid = (NBATCH * NS * 16) / TPB;          // 8192 blocks

    level_kernel<4096, 0><<<grid, TPB>>>(x,   lo1, out + 1 * PLANE, hf, scores);
    level_kernel<2048, 1><<<grid, TPB>>>(lo1, lo2, out + 2 * PLANE, hf, scores);
    level_kernel<1024, 2><<<grid, TPB>>>(lo2, lo3, out + 3 * PLANE, hf, scores);
    level_kernel< 512, 3><<<grid, TPB>>>(lo3, lo4, out + 4 * PLANE, hf, scores);
    level_kernel< 256, 4><<<grid, TPB>>>(lo4, lo5, out + 5 * PLANE, hf, scores);
    final_kernel<<<grid, TPB>>>(out, scores);
}